// round 6
// baseline (speedup 1.0000x reference)
#include <cuda_runtime.h>

#define B_    2
#define N_    512
#define DS_   384
#define DP_   128
#define H_    16
#define DH_   64
#define DI_   1024
#define MAXS_ 2048

// ---------------- scratch (static device globals; no allocs) ----------------
__device__ float g_bias[B_*H_*N_*N_];   // attn bias  [b][h][i][j]
__device__ float g_q[B_*H_*N_*DH_];     // [b][h][n][d]
__device__ float g_k[B_*H_*N_*DH_];
__device__ float g_v[B_*H_*N_*DH_];
__device__ float g_g[B_*N_*DI_];        // gate logits [b][n][di]
__device__ float g_o[B_*N_*DI_];        // attention out [b][n][di]
__device__ float g_part[2][B_*N_][DS_]; // split-K partials for output proj

// ---------------------------------------------------------------------------
// K1: fused LayerNorm + per-head bias projection + positional bias
// ---------------------------------------------------------------------------
__global__ __launch_bounds__(256) void k1_ln_bias(
    const float* __restrict__ pw, const float* __restrict__ gamma,
    const float* __restrict__ beta, const float* __restrict__ wb,
    const float* __restrict__ abb)
{
    __shared__ float Wt[H_][DP_];
    __shared__ float c1s[H_], c2s[H_];
    int tid = threadIdx.x;

    for (int idx = tid; idx < DP_*H_; idx += 256) {
        int d = idx >> 4, h = idx & 15;
        Wt[h][d] = gamma[d] * wb[d*H_ + h];
    }
    __syncthreads();
    if (tid < H_) {
        float a = 0.f, c = 0.f;
        for (int d = 0; d < DP_; d++) {
            a += Wt[tid][d];
            c += beta[d] * wb[d*H_ + tid];
        }
        c1s[tid] = a; c2s[tid] = c;
    }
    __syncthreads();

    int bi = blockIdx.x;            // b*N + i
    int i  = bi & (N_-1);
    int b  = bi >> 9;
    int j0 = tid;

    const float* row0 = pw + ((long)bi * N_ + j0) * DP_;
    const float* row1 = row0 + 256 * DP_;

    float acc0[H_], acc1[H_];
#pragma unroll
    for (int h = 0; h < H_; h++) { acc0[h] = 0.f; acc1[h] = 0.f; }
    float s10 = 0.f, s20 = 0.f, s11 = 0.f, s21 = 0.f;

    for (int dg = 0; dg < DP_/4; dg++) {
        float4 p0 = __ldg((const float4*)row0 + dg);
        float4 p1 = __ldg((const float4*)row1 + dg);
        s10 += p0.x + p0.y + p0.z + p0.w;
        s20 += p0.x*p0.x + p0.y*p0.y + p0.z*p0.z + p0.w*p0.w;
        s11 += p1.x + p1.y + p1.z + p1.w;
        s21 += p1.x*p1.x + p1.y*p1.y + p1.z*p1.z + p1.w*p1.w;
#pragma unroll
        for (int h = 0; h < H_; h++) {
            float4 w = *(const float4*)(&Wt[h][dg*4]);
            acc0[h] += p0.x*w.x + p0.y*w.y + p0.z*w.z + p0.w*w.w;
            acc1[h] += p1.x*w.x + p1.y*w.y + p1.z*w.z + p1.w*w.w;
        }
    }

    float mu0 = s10 * (1.f/DP_);
    float mu1 = s11 * (1.f/DP_);
    float r0  = rsqrtf(s20*(1.f/DP_) - mu0*mu0 + 1e-5f);
    float r1  = rsqrtf(s21*(1.f/DP_) - mu1*mu1 + 1e-5f);
    float pb0 = abb[i*MAXS_ + j0];
    float pb1 = abb[i*MAXS_ + j0 + 256];

    int base = ((b*H_)*N_ + i)*N_;
#pragma unroll
    for (int h = 0; h < H_; h++) {
        int o = base + h*(N_*N_);
        g_bias[o + j0]       = r0*(acc0[h] - mu0*c1s[h]) + c2s[h] + pb0;
        g_bias[o + j0 + 256] = r1*(acc1[h] - mu1*c1s[h]) + c2s[h] + pb1;
    }
}

// ---------------------------------------------------------------------------
// K2: QKV+G projections.  C = X[1024x384] @ W[z][384x1024].
// BM=64, BN=128, BK=16, 256 threads, 4x8 micro. grid (8,16,4)=512.
// ---------------------------------------------------------------------------
__global__ __launch_bounds__(256) void k2_qkvg(
    const float* __restrict__ X,
    const float* __restrict__ wq, const float* __restrict__ wk,
    const float* __restrict__ wv, const float* __restrict__ wg)
{
    __shared__ float As[16][65];     // A transposed [k][m], padded, scalar stores
    __shared__ float Bs[16][128];
    int z = blockIdx.z;
    const float* W = (z==0) ? wq : (z==1) ? wk : (z==2) ? wv : wg;
    int m0 = blockIdx.y * 64, n0 = blockIdx.x * 128;
    int tid = threadIdx.x;
    int tx = tid & 15, ty = tid >> 4;

    float acc[4][8];
#pragma unroll
    for (int a = 0; a < 4; a++)
#pragma unroll
        for (int c = 0; c < 8; c++) acc[a][c] = 0.f;

    int ar = tid >> 2, ac = (tid & 3) * 4;    // A: 64 rows x 16 k
    int bk = tid >> 5, bc = (tid & 31) * 4;   // B: rows bk,bk+8 x 128 n

    for (int k0 = 0; k0 < DS_; k0 += 16) {
        float4 av  = *(const float4*)(X + (m0+ar)*DS_ + k0 + ac);
        float4 bv0 = *(const float4*)(W + (k0+bk  )*DI_ + n0 + bc);
        float4 bv1 = *(const float4*)(W + (k0+bk+8)*DI_ + n0 + bc);
        __syncthreads();
        As[ac+0][ar] = av.x; As[ac+1][ar] = av.y;
        As[ac+2][ar] = av.z; As[ac+3][ar] = av.w;
        *(float4*)(&Bs[bk  ][bc]) = bv0;
        *(float4*)(&Bs[bk+8][bc]) = bv1;
        __syncthreads();
#pragma unroll
        for (int k = 0; k < 16; k++) {
            float a[4], bb[8];
            a[0] = As[k][ty*4+0]; a[1] = As[k][ty*4+1];
            a[2] = As[k][ty*4+2]; a[3] = As[k][ty*4+3];
            *(float4*)(&bb[0]) = *(const float4*)(&Bs[k][tx*8]);
            *(float4*)(&bb[4]) = *(const float4*)(&Bs[k][tx*8+4]);
#pragma unroll
            for (int im = 0; im < 4; im++)
#pragma unroll
                for (int in = 0; in < 8; in++)
                    acc[im][in] += a[im]*bb[in];
        }
    }

    if (z == 3) {
#pragma unroll
        for (int im = 0; im < 4; im++) {
            int m = m0 + ty*4 + im;
#pragma unroll
            for (int in = 0; in < 8; in++)
                g_g[m*DI_ + n0 + tx*8 + in] = acc[im][in];
        }
    } else {
        float* dst = (z==0) ? g_q : (z==1) ? g_k : g_v;
#pragma unroll
        for (int im = 0; im < 4; im++) {
            int m = m0 + ty*4 + im;
            int b = m >> 9, n = m & (N_-1);
#pragma unroll
            for (int in = 0; in < 8; in++) {
                int col = n0 + tx*8 + in;
                int h = col >> 6, dh = col & 63;
                dst[((b*H_ + h)*N_ + n)*DH_ + dh] = acc[im][in];
            }
        }
    }
}

// ---------------------------------------------------------------------------
// K35: fused attention per (b,h). scores + bias + online softmax + P@V.
// ---------------------------------------------------------------------------
__global__ __launch_bounds__(256) void k35_attn()
{
    __shared__ float Qs[64][65];
    __shared__ float Ks[32][65];
    __shared__ float Vs[32][64];
    __shared__ float Ps[32][65];

    int z  = blockIdx.y;                    // b*16 + h
    int i0 = blockIdx.x * 64;
    const float* Q  = g_q + (long)z * (N_*DH_);
    const float* K  = g_k + (long)z * (N_*DH_);
    const float* V  = g_v + (long)z * (N_*DH_);
    const float* Bb = g_bias + (long)z * N_ * N_;

    int tid = threadIdx.x;
    int ti = tid >> 4;
    int tj = tid & 15;

    {
        int r  = tid >> 2;
        int c0 = (tid & 3) * 16;
#pragma unroll
        for (int q = 0; q < 4; q++) {
            float4 v = *(const float4*)(Q + (i0 + r)*DH_ + c0 + q*4);
            Qs[r][c0 + q*4 + 0] = v.x;
            Qs[r][c0 + q*4 + 1] = v.y;
            Qs[r][c0 + q*4 + 2] = v.z;
            Qs[r][c0 + q*4 + 3] = v.w;
        }
    }

    float m_run[4], l_run[4], o[4][4];
#pragma unroll
    for (int a = 0; a < 4; a++) {
        m_run[a] = -1e30f; l_run[a] = 0.f;
#pragma unroll
        for (int c = 0; c < 4; c++) o[a][c] = 0.f;
    }
    __syncthreads();

    for (int j0 = 0; j0 < N_; j0 += 32) {
        {
            int r = tid >> 3;
            int c = (tid & 7) * 8;
            float4 ka = *(const float4*)(K + (j0 + r)*DH_ + c);
            float4 kb = *(const float4*)(K + (j0 + r)*DH_ + c + 4);
            float4 va = *(const float4*)(V + (j0 + r)*DH_ + c);
            float4 vb = *(const float4*)(V + (j0 + r)*DH_ + c + 4);
            Ks[r][c+0] = ka.x; Ks[r][c+1] = ka.y; Ks[r][c+2] = ka.z; Ks[r][c+3] = ka.w;
            Ks[r][c+4] = kb.x; Ks[r][c+5] = kb.y; Ks[r][c+6] = kb.z; Ks[r][c+7] = kb.w;
            *(float4*)(&Vs[r][c])   = va;
            *(float4*)(&Vs[r][c+4]) = vb;
        }
        __syncthreads();

        float s[4][2];
#pragma unroll
        for (int a = 0; a < 4; a++) { s[a][0] = 0.f; s[a][1] = 0.f; }
#pragma unroll 8
        for (int k = 0; k < 64; k++) {
            float a0 = Qs[ti*4+0][k], a1 = Qs[ti*4+1][k];
            float a2 = Qs[ti*4+2][k], a3 = Qs[ti*4+3][k];
            float b0 = Ks[tj*2+0][k], b1 = Ks[tj*2+1][k];
            s[0][0] += a0*b0; s[0][1] += a0*b1;
            s[1][0] += a1*b0; s[1][1] += a1*b1;
            s[2][0] += a2*b0; s[2][1] += a2*b1;
            s[3][0] += a3*b0; s[3][1] += a3*b1;
        }

#pragma unroll
        for (int a = 0; a < 4; a++) {
            const float* br = Bb + (long)(i0 + ti*4 + a)*N_ + j0 + tj*2;
            s[a][0] = s[a][0]*0.125f + br[0];
            s[a][1] = s[a][1]*0.125f + br[1];

            float cm = fmaxf(s[a][0], s[a][1]);
#pragma unroll
            for (int sft = 8; sft > 0; sft >>= 1)
                cm = fmaxf(cm, __shfl_xor_sync(0xffffffffu, cm, sft, 16));
            float mn = fmaxf(m_run[a], cm);
            float sc = __expf(m_run[a] - mn);
            float e0 = __expf(s[a][0] - mn);
            float e1 = __expf(s[a][1] - mn);
            float cs = e0 + e1;
#pragma unroll
            for (int sft = 8; sft > 0; sft >>= 1)
                cs += __shfl_xor_sync(0xffffffffu, cs, sft, 16);
            l_run[a] = l_run[a]*sc + cs;
            m_run[a] = mn;
#pragma unroll
            for (int c = 0; c < 4; c++) o[a][c] *= sc;
            s[a][0] = e0; s[a][1] = e1;
        }

#pragma unroll
        for (int a = 0; a < 4; a++) {
            Ps[tj*2+0][ti*4+a] = s[a][0];
            Ps[tj*2+1][ti*4+a] = s[a][1];
        }
        __syncthreads();

#pragma unroll 8
        for (int j = 0; j < 32; j++) {
            float p0 = Ps[j][ti*4+0], p1 = Ps[j][ti*4+1];
            float p2 = Ps[j][ti*4+2], p3 = Ps[j][ti*4+3];
            float4 bv = *(const float4*)(&Vs[j][tj*4]);
            o[0][0] += p0*bv.x; o[0][1] += p0*bv.y; o[0][2] += p0*bv.z; o[0][3] += p0*bv.w;
            o[1][0] += p1*bv.x; o[1][1] += p1*bv.y; o[1][2] += p1*bv.z; o[1][3] += p1*bv.w;
            o[2][0] += p2*bv.x; o[2][1] += p2*bv.y; o[2][2] += p2*bv.z; o[2][3] += p2*bv.w;
            o[3][0] += p3*bv.x; o[3][1] += p3*bv.y; o[3][2] += p3*bv.z; o[3][3] += p3*bv.w;
        }
        __syncthreads();
    }

    int b = z >> 4, h = z & 15;
#pragma unroll
    for (int a = 0; a < 4; a++) {
        float inv = 1.f / l_run[a];
        int i = i0 + ti*4 + a;
#pragma unroll
        for (int c = 0; c < 4; c++)
            g_o[(long)(b*N_ + i)*DI_ + h*DH_ + tj*4 + c] = o[a][c] * inv;
    }
}

// ---------------------------------------------------------------------------
// K6: out_part = (o * sigmoid(g)) @ w_o, SPLIT-K=2.
// BM=32, BN=64, BK=16, 256 threads, 2x4 micro. grid (6,32,2)=384 blocks.
// ---------------------------------------------------------------------------
__global__ __launch_bounds__(256) void k6_out(const float* __restrict__ wo)
{
    __shared__ float As[16][33];   // A transposed [k][m], padded, scalar stores
    __shared__ float Bs[16][64];
    int m0 = blockIdx.y * 32, n0 = blockIdx.x * 64;
    int kh = blockIdx.z;
    int kbase = kh * (DI_/2);
    int tid = threadIdx.x;
    int tx = tid & 15, ty = tid >> 4;
    int ar = tid >> 3, ac = (tid & 7) * 2;    // A: 32 rows x 16 k (float2 each)
    int bk = tid >> 4, bc = (tid & 15) * 4;   // B: 16 k x 64 n

    float acc[2][4];
#pragma unroll
    for (int a = 0; a < 2; a++)
#pragma unroll
        for (int c = 0; c < 4; c++) acc[a][c] = 0.f;

    for (int kk = 0; kk < DI_/2; kk += 16) {
        int k0 = kbase + kk;
        float2 ov = *(const float2*)(g_o + (m0+ar)*DI_ + k0 + ac);
        float2 gv = *(const float2*)(g_g + (m0+ar)*DI_ + k0 + ac);
        float4 bv = *(const float4*)(wo + (k0+bk)*DS_ + n0 + bc);
        float a0 = ov.x / (1.f + __expf(-gv.x));
        float a1 = ov.y / (1.f + __expf(-gv.y));
        __syncthreads();
        As[ac+0][ar] = a0;
        As[ac+1][ar] = a1;
        *(float4*)(&Bs[bk][bc]) = bv;
        __syncthreads();
#pragma unroll
        for (int k = 0; k < 16; k++) {
            float av0 = As[k][ty*2+0];
            float av1 = As[k][ty*2+1];
            float4 b  = *(const float4*)(&Bs[k][tx*4]);
            acc[0][0] += av0*b.x; acc[0][1] += av0*b.y; acc[0][2] += av0*b.z; acc[0][3] += av0*b.w;
            acc[1][0] += av1*b.x; acc[1][1] += av1*b.y; acc[1][2] += av1*b.z; acc[1][3] += av1*b.w;
        }
    }

#pragma unroll
    for (int ii = 0; ii < 2; ii++) {
        float4 v = make_float4(acc[ii][0], acc[ii][1], acc[ii][2], acc[ii][3]);
        *(float4*)(&g_part[kh][m0 + ty*2 + ii][n0 + tx*4]) = v;
    }
}

// ---------------------------------------------------------------------------
// K6R: out = part0 + part1. 1024*384 floats = 98304 float4.
// ---------------------------------------------------------------------------
__global__ __launch_bounds__(256) void k6_reduce(float* __restrict__ out)
{
    int idx = blockIdx.x * 256 + threadIdx.x;   // float4 index
    const float4* p0 = (const float4*)&g_part[0][0][0];
    const float4* p1 = (const float4*)&g_part[1][0][0];
    float4 a = p0[idx], b = p1[idx];
    float4 r = make_float4(a.x+b.x, a.y+b.y, a.z+b.z, a.w+b.w);
    ((float4*)out)[idx] = r;
}

// ---------------------------------------------------------------------------
extern "C" void kernel_launch(void* const* d_in, const int* in_sizes, int n_in,
                              void* d_out, int out_size) {
    const float* single = (const float*)d_in[0];
    const float* pw     = (const float*)d_in[1];
    const float* gamma  = (const float*)d_in[2];
    const float* beta   = (const float*)d_in[3];
    const float* wb     = (const float*)d_in[4];
    const float* abb    = (const float*)d_in[5];
    const float* wq     = (const float*)d_in[6];
    const float* wk     = (const float*)d_in[7];
    const float* wv     = (const float*)d_in[8];
    const float* wg     = (const float*)d_in[9];
    const float* wo     = (const float*)d_in[10];
    float* out = (float*)d_out;

    k1_ln_bias<<<B_*N_, 256>>>(pw, gamma, beta, wb, abb);
    k2_qkvg<<<dim3(8, 16, 4), 256>>>(single, wq, wk, wv, wg);
    k35_attn<<<dim3(8, 32), 256>>>();
    k6_out<<<dim3(6, 32, 2), 256>>>(wo);
    k6_reduce<<<(B_*N_*DS_)/(4*256), 256>>>(out);
}

// round 9
// speedup vs baseline: 1.0012x; 1.0012x over previous
#include <cuda_runtime.h>

#define B_    2
#define N_    512
#define DS_   384
#define DP_   128
#define H_    16
#define DH_   64
#define DI_   1024
#define MAXS_ 2048

// ---------------- scratch (static device globals; no allocs) ----------------
__device__ float g_bias[B_*H_*N_*N_];   // attn bias  [b][h][i][j]
__device__ float g_q[B_*H_*N_*DH_];     // [b][h][n][d]
__device__ float g_k[B_*H_*N_*DH_];
__device__ float g_v[B_*H_*N_*DH_];
__device__ float g_g[B_*N_*DI_];        // gate logits [b][n][di]
__device__ float g_o[B_*N_*DI_];        // attention out [b][n][di]
__device__ float g_part[2][B_*N_][DS_]; // split-K partials for output proj

// ---------------------------------------------------------------------------
// K1: fused LayerNorm + per-head bias projection + positional bias
// ---------------------------------------------------------------------------
__global__ __launch_bounds__(256) void k1_ln_bias(
    const float* __restrict__ pw, const float* __restrict__ gamma,
    const float* __restrict__ beta, const float* __restrict__ wb,
    const float* __restrict__ abb)
{
    __shared__ float Wt[H_][DP_];
    __shared__ float c1s[H_], c2s[H_];
    int tid = threadIdx.x;

    for (int idx = tid; idx < DP_*H_; idx += 256) {
        int d = idx >> 4, h = idx & 15;
        Wt[h][d] = gamma[d] * wb[d*H_ + h];
    }
    __syncthreads();
    if (tid < H_) {
        float a = 0.f, c = 0.f;
        for (int d = 0; d < DP_; d++) {
            a += Wt[tid][d];
            c += beta[d] * wb[d*H_ + tid];
        }
        c1s[tid] = a; c2s[tid] = c;
    }
    __syncthreads();

    int bi = blockIdx.x;            // b*N + i
    int i  = bi & (N_-1);
    int b  = bi >> 9;
    int j0 = tid;

    const float* row0 = pw + ((long)bi * N_ + j0) * DP_;
    const float* row1 = row0 + 256 * DP_;

    float acc0[H_], acc1[H_];
#pragma unroll
    for (int h = 0; h < H_; h++) { acc0[h] = 0.f; acc1[h] = 0.f; }
    float s10 = 0.f, s20 = 0.f, s11 = 0.f, s21 = 0.f;

    for (int dg = 0; dg < DP_/4; dg++) {
        float4 p0 = __ldg((const float4*)row0 + dg);
        float4 p1 = __ldg((const float4*)row1 + dg);
        s10 += p0.x + p0.y + p0.z + p0.w;
        s20 += p0.x*p0.x + p0.y*p0.y + p0.z*p0.z + p0.w*p0.w;
        s11 += p1.x + p1.y + p1.z + p1.w;
        s21 += p1.x*p1.x + p1.y*p1.y + p1.z*p1.z + p1.w*p1.w;
#pragma unroll
        for (int h = 0; h < H_; h++) {
            float4 w = *(const float4*)(&Wt[h][dg*4]);
            acc0[h] += p0.x*w.x + p0.y*w.y + p0.z*w.z + p0.w*w.w;
            acc1[h] += p1.x*w.x + p1.y*w.y + p1.z*w.z + p1.w*w.w;
        }
    }

    float mu0 = s10 * (1.f/DP_);
    float mu1 = s11 * (1.f/DP_);
    float r0  = rsqrtf(s20*(1.f/DP_) - mu0*mu0 + 1e-5f);
    float r1  = rsqrtf(s21*(1.f/DP_) - mu1*mu1 + 1e-5f);
    float pb0 = abb[i*MAXS_ + j0];
    float pb1 = abb[i*MAXS_ + j0 + 256];

    int base = ((b*H_)*N_ + i)*N_;
#pragma unroll
    for (int h = 0; h < H_; h++) {
        int o = base + h*(N_*N_);
        g_bias[o + j0]       = r0*(acc0[h] - mu0*c1s[h]) + c2s[h] + pb0;
        g_bias[o + j0 + 256] = r1*(acc1[h] - mu1*c1s[h]) + c2s[h] + pb1;
    }
}

// ---------------------------------------------------------------------------
// K2: QKV+G projections.  C = X[1024x384] @ W[z][384x1024].
// BM=64, BN=128, BK=16, 256 threads, 4x8 micro. grid (8,16,4)=512.
// ---------------------------------------------------------------------------
__global__ __launch_bounds__(256) void k2_qkvg(
    const float* __restrict__ X,
    const float* __restrict__ wq, const float* __restrict__ wk,
    const float* __restrict__ wv, const float* __restrict__ wg)
{
    __shared__ float As[16][65];     // A transposed [k][m], padded, scalar stores
    __shared__ float Bs[16][128];
    int z = blockIdx.z;
    const float* W = (z==0) ? wq : (z==1) ? wk : (z==2) ? wv : wg;
    int m0 = blockIdx.y * 64, n0 = blockIdx.x * 128;
    int tid = threadIdx.x;
    int tx = tid & 15, ty = tid >> 4;

    float acc[4][8];
#pragma unroll
    for (int a = 0; a < 4; a++)
#pragma unroll
        for (int c = 0; c < 8; c++) acc[a][c] = 0.f;

    int ar = tid >> 2, ac = (tid & 3) * 4;    // A: 64 rows x 16 k
    int bk = tid >> 5, bc = (tid & 31) * 4;   // B: rows bk,bk+8 x 128 n

    for (int k0 = 0; k0 < DS_; k0 += 16) {
        float4 av  = *(const float4*)(X + (m0+ar)*DS_ + k0 + ac);
        float4 bv0 = *(const float4*)(W + (k0+bk  )*DI_ + n0 + bc);
        float4 bv1 = *(const float4*)(W + (k0+bk+8)*DI_ + n0 + bc);
        __syncthreads();
        As[ac+0][ar] = av.x; As[ac+1][ar] = av.y;
        As[ac+2][ar] = av.z; As[ac+3][ar] = av.w;
        *(float4*)(&Bs[bk  ][bc]) = bv0;
        *(float4*)(&Bs[bk+8][bc]) = bv1;
        __syncthreads();
#pragma unroll
        for (int k = 0; k < 16; k++) {
            float a[4], bb[8];
            a[0] = As[k][ty*4+0]; a[1] = As[k][ty*4+1];
            a[2] = As[k][ty*4+2]; a[3] = As[k][ty*4+3];
            *(float4*)(&bb[0]) = *(const float4*)(&Bs[k][tx*8]);
            *(float4*)(&bb[4]) = *(const float4*)(&Bs[k][tx*8+4]);
#pragma unroll
            for (int im = 0; im < 4; im++)
#pragma unroll
                for (int in = 0; in < 8; in++)
                    acc[im][in] += a[im]*bb[in];
        }
    }

    if (z == 3) {
#pragma unroll
        for (int im = 0; im < 4; im++) {
            int m = m0 + ty*4 + im;
#pragma unroll
            for (int in = 0; in < 8; in++)
                g_g[m*DI_ + n0 + tx*8 + in] = acc[im][in];
        }
    } else {
        float* dst = (z==0) ? g_q : (z==1) ? g_k : g_v;
#pragma unroll
        for (int im = 0; im < 4; im++) {
            int m = m0 + ty*4 + im;
            int b = m >> 9, n = m & (N_-1);
#pragma unroll
            for (int in = 0; in < 8; in++) {
                int col = n0 + tx*8 + in;
                int h = col >> 6, dh = col & 63;
                dst[((b*H_ + h)*N_ + n)*DH_ + dh] = acc[im][in];
            }
        }
    }
}

// ---------------------------------------------------------------------------
// K35: fused attention per (b,h). scores + bias + online softmax + P@V.
// ---------------------------------------------------------------------------
__global__ __launch_bounds__(256) void k35_attn()
{
    __shared__ float Qs[64][65];
    __shared__ float Ks[32][65];
    __shared__ float Vs[32][64];
    __shared__ float Ps[32][65];

    int z  = blockIdx.y;                    // b*16 + h
    int i0 = blockIdx.x * 64;
    const float* Q  = g_q + (long)z * (N_*DH_);
    const float* K  = g_k + (long)z * (N_*DH_);
    const float* V  = g_v + (long)z * (N_*DH_);
    const float* Bb = g_bias + (long)z * N_ * N_;

    int tid = threadIdx.x;
    int ti = tid >> 4;
    int tj = tid & 15;

    {
        int r  = tid >> 2;
        int c0 = (tid & 3) * 16;
#pragma unroll
        for (int q = 0; q < 4; q++) {
            float4 v = *(const float4*)(Q + (i0 + r)*DH_ + c0 + q*4);
            Qs[r][c0 + q*4 + 0] = v.x;
            Qs[r][c0 + q*4 + 1] = v.y;
            Qs[r][c0 + q*4 + 2] = v.z;
            Qs[r][c0 + q*4 + 3] = v.w;
        }
    }

    float m_run[4], l_run[4], o[4][4];
#pragma unroll
    for (int a = 0; a < 4; a++) {
        m_run[a] = -1e30f; l_run[a] = 0.f;
#pragma unroll
        for (int c = 0; c < 4; c++) o[a][c] = 0.f;
    }
    __syncthreads();

    for (int j0 = 0; j0 < N_; j0 += 32) {
        {
            int r = tid >> 3;
            int c = (tid & 7) * 8;
            float4 ka = *(const float4*)(K + (j0 + r)*DH_ + c);
            float4 kb = *(const float4*)(K + (j0 + r)*DH_ + c + 4);
            float4 va = *(const float4*)(V + (j0 + r)*DH_ + c);
            float4 vb = *(const float4*)(V + (j0 + r)*DH_ + c + 4);
            Ks[r][c+0] = ka.x; Ks[r][c+1] = ka.y; Ks[r][c+2] = ka.z; Ks[r][c+3] = ka.w;
            Ks[r][c+4] = kb.x; Ks[r][c+5] = kb.y; Ks[r][c+6] = kb.z; Ks[r][c+7] = kb.w;
            *(float4*)(&Vs[r][c])   = va;
            *(float4*)(&Vs[r][c+4]) = vb;
        }
        __syncthreads();

        float s[4][2];
#pragma unroll
        for (int a = 0; a < 4; a++) { s[a][0] = 0.f; s[a][1] = 0.f; }
#pragma unroll 8
        for (int k = 0; k < 64; k++) {
            float a0 = Qs[ti*4+0][k], a1 = Qs[ti*4+1][k];
            float a2 = Qs[ti*4+2][k], a3 = Qs[ti*4+3][k];
            float b0 = Ks[tj*2+0][k], b1 = Ks[tj*2+1][k];
            s[0][0] += a0*b0; s[0][1] += a0*b1;
            s[1][0] += a1*b0; s[1][1] += a1*b1;
            s[2][0] += a2*b0; s[2][1] += a2*b1;
            s[3][0] += a3*b0; s[3][1] += a3*b1;
        }

#pragma unroll
        for (int a = 0; a < 4; a++) {
            const float* br = Bb + (long)(i0 + ti*4 + a)*N_ + j0 + tj*2;
            s[a][0] = s[a][0]*0.125f + br[0];
            s[a][1] = s[a][1]*0.125f + br[1];

            float cm = fmaxf(s[a][0], s[a][1]);
#pragma unroll
            for (int sft = 8; sft > 0; sft >>= 1)
                cm = fmaxf(cm, __shfl_xor_sync(0xffffffffu, cm, sft, 16));
            float mn = fmaxf(m_run[a], cm);
            float sc = __expf(m_run[a] - mn);
            float e0 = __expf(s[a][0] - mn);
            float e1 = __expf(s[a][1] - mn);
            float cs = e0 + e1;
#pragma unroll
            for (int sft = 8; sft > 0; sft >>= 1)
                cs += __shfl_xor_sync(0xffffffffu, cs, sft, 16);
            l_run[a] = l_run[a]*sc + cs;
            m_run[a] = mn;
#pragma unroll
            for (int c = 0; c < 4; c++) o[a][c] *= sc;
            s[a][0] = e0; s[a][1] = e1;
        }

#pragma unroll
        for (int a = 0; a < 4; a++) {
            Ps[tj*2+0][ti*4+a] = s[a][0];
            Ps[tj*2+1][ti*4+a] = s[a][1];
        }
        __syncthreads();

#pragma unroll 8
        for (int j = 0; j < 32; j++) {
            float p0 = Ps[j][ti*4+0], p1 = Ps[j][ti*4+1];
            float p2 = Ps[j][ti*4+2], p3 = Ps[j][ti*4+3];
            float4 bv = *(const float4*)(&Vs[j][tj*4]);
            o[0][0] += p0*bv.x; o[0][1] += p0*bv.y; o[0][2] += p0*bv.z; o[0][3] += p0*bv.w;
            o[1][0] += p1*bv.x; o[1][1] += p1*bv.y; o[1][2] += p1*bv.z; o[1][3] += p1*bv.w;
            o[2][0] += p2*bv.x; o[2][1] += p2*bv.y; o[2][2] += p2*bv.z; o[2][3] += p2*bv.w;
            o[3][0] += p3*bv.x; o[3][1] += p3*bv.y; o[3][2] += p3*bv.z; o[3][3] += p3*bv.w;
        }
        __syncthreads();
    }

    int b = z >> 4, h = z & 15;
#pragma unroll
    for (int a = 0; a < 4; a++) {
        float inv = 1.f / l_run[a];
        int i = i0 + ti*4 + a;
#pragma unroll
        for (int c = 0; c < 4; c++)
            g_o[(long)(b*N_ + i)*DI_ + h*DH_ + tj*4 + c] = o[a][c] * inv;
    }
}

// ---------------------------------------------------------------------------
// K6: out_part = (o * sigmoid(g)) @ w_o, SPLIT-K=2.
// BM=32, BN=64, BK=16, 256 threads, 2x4 micro. grid (6,32,2)=384 blocks.
// ---------------------------------------------------------------------------
__global__ __launch_bounds__(256) void k6_out(const float* __restrict__ wo)
{
    __shared__ float As[16][33];   // A transposed [k][m], padded, scalar stores
    __shared__ float Bs[16][64];
    int m0 = blockIdx.y * 32, n0 = blockIdx.x * 64;
    int kh = blockIdx.z;
    int kbase = kh * (DI_/2);
    int tid = threadIdx.x;
    int tx = tid & 15, ty = tid >> 4;
    int ar = tid >> 3, ac = (tid & 7) * 2;    // A: 32 rows x 16 k (float2 each)
    int bk = tid >> 4, bc = (tid & 15) * 4;   // B: 16 k x 64 n

    float acc[2][4];
#pragma unroll
    for (int a = 0; a < 2; a++)
#pragma unroll
        for (int c = 0; c < 4; c++) acc[a][c] = 0.f;

    for (int kk = 0; kk < DI_/2; kk += 16) {
        int k0 = kbase + kk;
        float2 ov = *(const float2*)(g_o + (m0+ar)*DI_ + k0 + ac);
        float2 gv = *(const float2*)(g_g + (m0+ar)*DI_ + k0 + ac);
        float4 bv = *(const float4*)(wo + (k0+bk)*DS_ + n0 + bc);
        float a0 = ov.x / (1.f + __expf(-gv.x));
        float a1 = ov.y / (1.f + __expf(-gv.y));
        __syncthreads();
        As[ac+0][ar] = a0;
        As[ac+1][ar] = a1;
        *(float4*)(&Bs[bk][bc]) = bv;
        __syncthreads();
#pragma unroll
        for (int k = 0; k < 16; k++) {
            float av0 = As[k][ty*2+0];
            float av1 = As[k][ty*2+1];
            float4 b  = *(const float4*)(&Bs[k][tx*4]);
            acc[0][0] += av0*b.x; acc[0][1] += av0*b.y; acc[0][2] += av0*b.z; acc[0][3] += av0*b.w;
            acc[1][0] += av1*b.x; acc[1][1] += av1*b.y; acc[1][2] += av1*b.z; acc[1][3] += av1*b.w;
        }
    }

#pragma unroll
    for (int ii = 0; ii < 2; ii++) {
        float4 v = make_float4(acc[ii][0], acc[ii][1], acc[ii][2], acc[ii][3]);
        *(float4*)(&g_part[kh][m0 + ty*2 + ii][n0 + tx*4]) = v;
    }
}

// ---------------------------------------------------------------------------
// K6R: out = part0 + part1. 1024*384 floats = 98304 float4.
// ---------------------------------------------------------------------------
__global__ __launch_bounds__(256) void k6_reduce(float* __restrict__ out)
{
    int idx = blockIdx.x * 256 + threadIdx.x;   // float4 index
    const float4* p0 = (const float4*)&g_part[0][0][0];
    const float4* p1 = (const float4*)&g_part[1][0][0];
    float4 a = p0[idx], b = p1[idx];
    float4 r = make_float4(a.x+b.x, a.y+b.y, a.z+b.z, a.w+b.w);
    ((float4*)out)[idx] = r;
}

// ---------------------------------------------------------------------------
extern "C" void kernel_launch(void* const* d_in, const int* in_sizes, int n_in,
                              void* d_out, int out_size) {
    const float* single = (const float*)d_in[0];
    const float* pw     = (const float*)d_in[1];
    const float* gamma  = (const float*)d_in[2];
    const float* beta   = (const float*)d_in[3];
    const float* wb     = (const float*)d_in[4];
    const float* abb    = (const float*)d_in[5];
    const float* wq     = (const float*)d_in[6];
    const float* wk     = (const float*)d_in[7];
    const float* wv     = (const float*)d_in[8];
    const float* wg     = (const float*)d_in[9];
    const float* wo     = (const float*)d_in[10];
    float* out = (float*)d_out;

    k1_ln_bias<<<B_*N_, 256>>>(pw, gamma, beta, wb, abb);
    k2_qkvg<<<dim3(8, 16, 4), 256>>>(single, wq, wk, wv, wg);
    k35_attn<<<dim3(8, 32), 256>>>();
    k6_out<<<dim3(6, 32, 2), 256>>>(wo);
    k6_reduce<<<(B_*N_*DS_)/(4*256), 256>>>(out);
}

// round 12
// speedup vs baseline: 1.1203x; 1.1189x over previous
#include <cuda_runtime.h>

#define B_    2
#define N_    512
#define DS_   384
#define DP_   128
#define H_    16
#define DH_   64
#define DI_   1024
#define MAXS_ 2048

// ---------------- scratch (static device globals; no allocs) ----------------
__device__ float g_bias[B_*H_*N_*N_];   // attn bias  [b][h][i][j]
__device__ float g_q[B_*H_*N_*DH_];     // [b][h][n][d]
__device__ float g_k[B_*H_*N_*DH_];
__device__ float g_v[B_*H_*N_*DH_];
__device__ float g_g[B_*N_*DI_];        // gate logits [b][n][di]
__device__ float g_o[B_*N_*DI_];        // attention out [b][n][di]
__device__ float g_part[2][B_*N_][DS_]; // split-K partials for output proj

// ---------------------------------------------------------------------------
// K1: fused LayerNorm + per-head bias projection + positional bias
// ---------------------------------------------------------------------------
__global__ __launch_bounds__(256) void k1_ln_bias(
    const float* __restrict__ pw, const float* __restrict__ gamma,
    const float* __restrict__ beta, const float* __restrict__ wb,
    const float* __restrict__ abb)
{
    __shared__ float Wt[H_][DP_];
    __shared__ float c1s[H_], c2s[H_];
    int tid = threadIdx.x;

    for (int idx = tid; idx < DP_*H_; idx += 256) {
        int d = idx >> 4, h = idx & 15;
        Wt[h][d] = gamma[d] * wb[d*H_ + h];
    }
    __syncthreads();
    if (tid < H_) {
        float a = 0.f, c = 0.f;
        for (int d = 0; d < DP_; d++) {
            a += Wt[tid][d];
            c += beta[d] * wb[d*H_ + tid];
        }
        c1s[tid] = a; c2s[tid] = c;
    }
    __syncthreads();

    int bi = blockIdx.x;            // b*N + i
    int i  = bi & (N_-1);
    int b  = bi >> 9;
    int j0 = tid;

    const float* row0 = pw + ((long)bi * N_ + j0) * DP_;
    const float* row1 = row0 + 256 * DP_;

    float acc0[H_], acc1[H_];
#pragma unroll
    for (int h = 0; h < H_; h++) { acc0[h] = 0.f; acc1[h] = 0.f; }
    float s10 = 0.f, s20 = 0.f, s11 = 0.f, s21 = 0.f;

    for (int dg = 0; dg < DP_/4; dg++) {
        float4 p0 = __ldg((const float4*)row0 + dg);
        float4 p1 = __ldg((const float4*)row1 + dg);
        s10 += p0.x + p0.y + p0.z + p0.w;
        s20 += p0.x*p0.x + p0.y*p0.y + p0.z*p0.z + p0.w*p0.w;
        s11 += p1.x + p1.y + p1.z + p1.w;
        s21 += p1.x*p1.x + p1.y*p1.y + p1.z*p1.z + p1.w*p1.w;
#pragma unroll
        for (int h = 0; h < H_; h++) {
            float4 w = *(const float4*)(&Wt[h][dg*4]);
            acc0[h] += p0.x*w.x + p0.y*w.y + p0.z*w.z + p0.w*w.w;
            acc1[h] += p1.x*w.x + p1.y*w.y + p1.z*w.z + p1.w*w.w;
        }
    }

    float mu0 = s10 * (1.f/DP_);
    float mu1 = s11 * (1.f/DP_);
    float r0  = rsqrtf(s20*(1.f/DP_) - mu0*mu0 + 1e-5f);
    float r1  = rsqrtf(s21*(1.f/DP_) - mu1*mu1 + 1e-5f);
    float pb0 = abb[i*MAXS_ + j0];
    float pb1 = abb[i*MAXS_ + j0 + 256];

    int base = ((b*H_)*N_ + i)*N_;
#pragma unroll
    for (int h = 0; h < H_; h++) {
        int o = base + h*(N_*N_);
        g_bias[o + j0]       = r0*(acc0[h] - mu0*c1s[h]) + c2s[h] + pb0;
        g_bias[o + j0 + 256] = r1*(acc1[h] - mu1*c1s[h]) + c2s[h] + pb1;
    }
}

// ---------------------------------------------------------------------------
// K2: QKV+G projections.  C = X[1024x384] @ W[z][384x1024].
// Round-4 proven config: 128x128 tile, BK=8, 8x8 micro, grid (8,8,4).
// 64 FMA per 4 LDS.128 per k -> FMA:LDS = 16.
// ---------------------------------------------------------------------------
__global__ __launch_bounds__(256) void k2_qkvg(
    const float* __restrict__ X,
    const float* __restrict__ wq, const float* __restrict__ wk,
    const float* __restrict__ wv, const float* __restrict__ wg)
{
    __shared__ float As[8][128];
    __shared__ float Bs[8][128];
    int z = blockIdx.z;
    const float* W = (z==0) ? wq : (z==1) ? wk : (z==2) ? wv : wg;
    int m0 = blockIdx.y * 128, n0 = blockIdx.x * 128;
    int tid = threadIdx.x;
    int tx = tid & 15, ty = tid >> 4;

    float acc[8][8];
#pragma unroll
    for (int a = 0; a < 8; a++)
#pragma unroll
        for (int c = 0; c < 8; c++) acc[a][c] = 0.f;

    int ar = tid >> 1, ac = (tid & 1) * 4;
    int bk = tid >> 5, bc = (tid & 31) * 4;

    for (int k0 = 0; k0 < DS_; k0 += 8) {
        float4 av = *(const float4*)(X + (m0+ar)*DS_ + k0 + ac);
        float4 bv = *(const float4*)(W + (k0+bk)*DI_ + n0 + bc);
        __syncthreads();
        As[ac+0][ar] = av.x; As[ac+1][ar] = av.y;
        As[ac+2][ar] = av.z; As[ac+3][ar] = av.w;
        *(float4*)(&Bs[bk][bc]) = bv;
        __syncthreads();
#pragma unroll
        for (int k = 0; k < 8; k++) {
            float a[8], bb[8];
            *(float4*)(&a[0])  = *(const float4*)(&As[k][ty*8]);
            *(float4*)(&a[4])  = *(const float4*)(&As[k][ty*8+4]);
            *(float4*)(&bb[0]) = *(const float4*)(&Bs[k][tx*8]);
            *(float4*)(&bb[4]) = *(const float4*)(&Bs[k][tx*8+4]);
#pragma unroll
            for (int im = 0; im < 8; im++)
#pragma unroll
                for (int in = 0; in < 8; in++)
                    acc[im][in] += a[im]*bb[in];
        }
    }

    if (z == 3) {
#pragma unroll
        for (int im = 0; im < 8; im++) {
            int m = m0 + ty*8 + im;
#pragma unroll
            for (int in = 0; in < 8; in++)
                g_g[m*DI_ + n0 + tx*8 + in] = acc[im][in];
        }
    } else {
        float* dst = (z==0) ? g_q : (z==1) ? g_k : g_v;
#pragma unroll
        for (int im = 0; im < 8; im++) {
            int m = m0 + ty*8 + im;
            int b = m >> 9, n = m & (N_-1);
#pragma unroll
            for (int in = 0; in < 8; in++) {
                int col = n0 + tx*8 + in;
                int h = col >> 6, dh = col & 63;
                dst[((b*H_ + h)*N_ + n)*DH_ + dh] = acc[im][in];
            }
        }
    }
}

// ---------------------------------------------------------------------------
// K35: fused attention per (b,h). scores + bias + online softmax + P@V.
// ---------------------------------------------------------------------------
__global__ __launch_bounds__(256) void k35_attn()
{
    __shared__ float Qs[64][65];
    __shared__ float Ks[32][65];
    __shared__ float Vs[32][64];
    __shared__ float Ps[32][65];

    int z  = blockIdx.y;                    // b*16 + h
    int i0 = blockIdx.x * 64;
    const float* Q  = g_q + (long)z * (N_*DH_);
    const float* K  = g_k + (long)z * (N_*DH_);
    const float* V  = g_v + (long)z * (N_*DH_);
    const float* Bb = g_bias + (long)z * N_ * N_;

    int tid = threadIdx.x;
    int ti = tid >> 4;
    int tj = tid & 15;

    {
        int r  = tid >> 2;
        int c0 = (tid & 3) * 16;
#pragma unroll
        for (int q = 0; q < 4; q++) {
            float4 v = *(const float4*)(Q + (i0 + r)*DH_ + c0 + q*4);
            Qs[r][c0 + q*4 + 0] = v.x;
            Qs[r][c0 + q*4 + 1] = v.y;
            Qs[r][c0 + q*4 + 2] = v.z;
            Qs[r][c0 + q*4 + 3] = v.w;
        }
    }

    float m_run[4], l_run[4], o[4][4];
#pragma unroll
    for (int a = 0; a < 4; a++) {
        m_run[a] = -1e30f; l_run[a] = 0.f;
#pragma unroll
        for (int c = 0; c < 4; c++) o[a][c] = 0.f;
    }
    __syncthreads();

    for (int j0 = 0; j0 < N_; j0 += 32) {
        {
            int r = tid >> 3;
            int c = (tid & 7) * 8;
            float4 ka = *(const float4*)(K + (j0 + r)*DH_ + c);
            float4 kb = *(const float4*)(K + (j0 + r)*DH_ + c + 4);
            float4 va = *(const float4*)(V + (j0 + r)*DH_ + c);
            float4 vb = *(const float4*)(V + (j0 + r)*DH_ + c + 4);
            Ks[r][c+0] = ka.x; Ks[r][c+1] = ka.y; Ks[r][c+2] = ka.z; Ks[r][c+3] = ka.w;
            Ks[r][c+4] = kb.x; Ks[r][c+5] = kb.y; Ks[r][c+6] = kb.z; Ks[r][c+7] = kb.w;
            *(float4*)(&Vs[r][c])   = va;
            *(float4*)(&Vs[r][c+4]) = vb;
        }
        __syncthreads();

        float s[4][2];
#pragma unroll
        for (int a = 0; a < 4; a++) { s[a][0] = 0.f; s[a][1] = 0.f; }
#pragma unroll 8
        for (int k = 0; k < 64; k++) {
            float a0 = Qs[ti*4+0][k], a1 = Qs[ti*4+1][k];
            float a2 = Qs[ti*4+2][k], a3 = Qs[ti*4+3][k];
            float b0 = Ks[tj*2+0][k], b1 = Ks[tj*2+1][k];
            s[0][0] += a0*b0; s[0][1] += a0*b1;
            s[1][0] += a1*b0; s[1][1] += a1*b1;
            s[2][0] += a2*b0; s[2][1] += a2*b1;
            s[3][0] += a3*b0; s[3][1] += a3*b1;
        }

#pragma unroll
        for (int a = 0; a < 4; a++) {
            const float* br = Bb + (long)(i0 + ti*4 + a)*N_ + j0 + tj*2;
            s[a][0] = s[a][0]*0.125f + br[0];
            s[a][1] = s[a][1]*0.125f + br[1];

            float cm = fmaxf(s[a][0], s[a][1]);
#pragma unroll
            for (int sft = 8; sft > 0; sft >>= 1)
                cm = fmaxf(cm, __shfl_xor_sync(0xffffffffu, cm, sft, 16));
            float mn = fmaxf(m_run[a], cm);
            float sc = __expf(m_run[a] - mn);
            float e0 = __expf(s[a][0] - mn);
            float e1 = __expf(s[a][1] - mn);
            float cs = e0 + e1;
#pragma unroll
            for (int sft = 8; sft > 0; sft >>= 1)
                cs += __shfl_xor_sync(0xffffffffu, cs, sft, 16);
            l_run[a] = l_run[a]*sc + cs;
            m_run[a] = mn;
#pragma unroll
            for (int c = 0; c < 4; c++) o[a][c] *= sc;
            s[a][0] = e0; s[a][1] = e1;
        }

#pragma unroll
        for (int a = 0; a < 4; a++) {
            Ps[tj*2+0][ti*4+a] = s[a][0];
            Ps[tj*2+1][ti*4+a] = s[a][1];
        }
        __syncthreads();

#pragma unroll 8
        for (int j = 0; j < 32; j++) {
            float p0 = Ps[j][ti*4+0], p1 = Ps[j][ti*4+1];
            float p2 = Ps[j][ti*4+2], p3 = Ps[j][ti*4+3];
            float4 bv = *(const float4*)(&Vs[j][tj*4]);
            o[0][0] += p0*bv.x; o[0][1] += p0*bv.y; o[0][2] += p0*bv.z; o[0][3] += p0*bv.w;
            o[1][0] += p1*bv.x; o[1][1] += p1*bv.y; o[1][2] += p1*bv.z; o[1][3] += p1*bv.w;
            o[2][0] += p2*bv.x; o[2][1] += p2*bv.y; o[2][2] += p2*bv.z; o[2][3] += p2*bv.w;
            o[3][0] += p3*bv.x; o[3][1] += p3*bv.y; o[3][2] += p3*bv.z; o[3][3] += p3*bv.w;
        }
        __syncthreads();
    }

    int b = z >> 4, h = z & 15;
#pragma unroll
    for (int a = 0; a < 4; a++) {
        float inv = 1.f / l_run[a];
        int i = i0 + ti*4 + a;
#pragma unroll
        for (int c = 0; c < 4; c++)
            g_o[(long)(b*N_ + i)*DI_ + h*DH_ + tj*4 + c] = o[a][c] * inv;
    }
}

// ---------------------------------------------------------------------------
// K6: out_part = (o * sigmoid(g)) @ w_o, SPLIT-K=2 with 4x4 microtile.
// BM=64, BN=64, BK=16, 256 threads. grid (6,16,2)=192 blocks.
// 16 FMA per 2 LDS.128 per k (ratio 8) vs prior 2x4 micro's ratio 2.7
// (L1 was 68.7% -> smem-pipe-bound). Keeps split-K occupancy win.
// ---------------------------------------------------------------------------
__global__ __launch_bounds__(256) void k6_out(const float* __restrict__ wo)
{
    __shared__ float As[16][68];   // transposed [k][m]; pitch 68 -> float4-aligned reads
    __shared__ float Bs[16][64];
    int m0 = blockIdx.y * 64, n0 = blockIdx.x * 64;
    int kh = blockIdx.z;
    int kbase = kh * (DI_/2);
    int tid = threadIdx.x;
    int tx = tid & 15, ty = tid >> 4;
    int ar = tid >> 2, ac = (tid & 3) * 4;    // A: 64 rows x 16 k
    int bk = tid >> 4, bc = (tid & 15) * 4;   // B: 16 k x 64 n

    float acc[4][4];
#pragma unroll
    for (int a = 0; a < 4; a++)
#pragma unroll
        for (int c = 0; c < 4; c++) acc[a][c] = 0.f;

    for (int kk = 0; kk < DI_/2; kk += 16) {
        int k0 = kbase + kk;
        float4 ov = *(const float4*)(g_o + (m0+ar)*DI_ + k0 + ac);
        float4 gv = *(const float4*)(g_g + (m0+ar)*DI_ + k0 + ac);
        float4 bv = *(const float4*)(wo + (k0+bk)*DS_ + n0 + bc);
        float4 a;
        a.x = ov.x / (1.f + __expf(-gv.x));
        a.y = ov.y / (1.f + __expf(-gv.y));
        a.z = ov.z / (1.f + __expf(-gv.z));
        a.w = ov.w / (1.f + __expf(-gv.w));
        __syncthreads();
        As[ac+0][ar] = a.x; As[ac+1][ar] = a.y;
        As[ac+2][ar] = a.z; As[ac+3][ar] = a.w;
        *(float4*)(&Bs[bk][bc]) = bv;
        __syncthreads();
#pragma unroll
        for (int k = 0; k < 16; k++) {
            float4 av = *(const float4*)(&As[k][ty*4]);
            float4 b  = *(const float4*)(&Bs[k][tx*4]);
            acc[0][0] += av.x*b.x; acc[0][1] += av.x*b.y; acc[0][2] += av.x*b.z; acc[0][3] += av.x*b.w;
            acc[1][0] += av.y*b.x; acc[1][1] += av.y*b.y; acc[1][2] += av.y*b.z; acc[1][3] += av.y*b.w;
            acc[2][0] += av.z*b.x; acc[2][1] += av.z*b.y; acc[2][2] += av.z*b.z; acc[2][3] += av.z*b.w;
            acc[3][0] += av.w*b.x; acc[3][1] += av.w*b.y; acc[3][2] += av.w*b.z; acc[3][3] += av.w*b.w;
        }
    }

#pragma unroll
    for (int ii = 0; ii < 4; ii++) {
        float4 v = make_float4(acc[ii][0], acc[ii][1], acc[ii][2], acc[ii][3]);
        *(float4*)(&g_part[kh][m0 + ty*4 + ii][n0 + tx*4]) = v;
    }
}

// ---------------------------------------------------------------------------
// K6R: out = part0 + part1. 1024*384 floats = 98304 float4.
// ---------------------------------------------------------------------------
__global__ __launch_bounds__(256) void k6_reduce(float* __restrict__ out)
{
    int idx = blockIdx.x * 256 + threadIdx.x;   // float4 index
    const float4* p0 = (const float4*)&g_part[0][0][0];
    const float4* p1 = (const float4*)&g_part[1][0][0];
    float4 a = p0[idx], b = p1[idx];
    float4 r = make_float4(a.x+b.x, a.y+b.y, a.z+b.z, a.w+b.w);
    ((float4*)out)[idx] = r;
}

// ---------------------------------------------------------------------------
extern "C" void kernel_launch(void* const* d_in, const int* in_sizes, int n_in,
                              void* d_out, int out_size) {
    const float* single = (const float*)d_in[0];
    const float* pw     = (const float*)d_in[1];
    const float* gamma  = (const float*)d_in[2];
    const float* beta   = (const float*)d_in[3];
    const float* wb     = (const float*)d_in[4];
    const float* abb    = (const float*)d_in[5];
    const float* wq     = (const float*)d_in[6];
    const float* wk     = (const float*)d_in[7];
    const float* wv     = (const float*)d_in[8];
    const float* wg     = (const float*)d_in[9];
    const float* wo     = (const float*)d_in[10];
    float* out = (float*)d_out;

    k1_ln_bias<<<B_*N_, 256>>>(pw, gamma, beta, wb, abb);
    k2_qkvg<<<dim3(8, 8, 4), 256>>>(single, wq, wk, wv, wg);
    k35_attn<<<dim3(8, 32), 256>>>();
    k6_out<<<dim3(6, 16, 2), 256>>>(wo);
    k6_reduce<<<(B_*N_*DS_)/(4*256), 256>>>(out);
}

// round 14
// speedup vs baseline: 1.1387x; 1.0165x over previous
#include <cuda_runtime.h>

#define B_    2
#define N_    512
#define DS_   384
#define DP_   128
#define H_    16
#define DH_   64
#define DI_   1024
#define MAXS_ 2048

// ---------------- scratch (static device globals; no allocs) ----------------
__device__ float g_bias[B_*H_*N_*N_];   // attn bias  [b][h][i][j]
__device__ float g_q[B_*H_*N_*DH_];     // [b][h][n][d]
__device__ float g_k[B_*H_*N_*DH_];
__device__ float g_v[B_*H_*N_*DH_];
__device__ float g_g[B_*N_*DI_];        // gate logits [b][n][di]
__device__ float g_o[B_*N_*DI_];        // attention out [b][n][di]
__device__ float g_part[4][B_*N_][DS_]; // split-K partials for output proj

// ---------------------------------------------------------------------------
// K1: fused LayerNorm + per-head bias projection + positional bias
// ---------------------------------------------------------------------------
__global__ __launch_bounds__(256) void k1_ln_bias(
    const float* __restrict__ pw, const float* __restrict__ gamma,
    const float* __restrict__ beta, const float* __restrict__ wb,
    const float* __restrict__ abb)
{
    __shared__ float Wt[H_][DP_];
    __shared__ float c1s[H_], c2s[H_];
    int tid = threadIdx.x;

    for (int idx = tid; idx < DP_*H_; idx += 256) {
        int d = idx >> 4, h = idx & 15;
        Wt[h][d] = gamma[d] * wb[d*H_ + h];
    }
    __syncthreads();
    if (tid < H_) {
        float a = 0.f, c = 0.f;
        for (int d = 0; d < DP_; d++) {
            a += Wt[tid][d];
            c += beta[d] * wb[d*H_ + tid];
        }
        c1s[tid] = a; c2s[tid] = c;
    }
    __syncthreads();

    int bi = blockIdx.x;            // b*N + i
    int i  = bi & (N_-1);
    int b  = bi >> 9;
    int j0 = tid;

    const float* row0 = pw + ((long)bi * N_ + j0) * DP_;
    const float* row1 = row0 + 256 * DP_;

    float acc0[H_], acc1[H_];
#pragma unroll
    for (int h = 0; h < H_; h++) { acc0[h] = 0.f; acc1[h] = 0.f; }
    float s10 = 0.f, s20 = 0.f, s11 = 0.f, s21 = 0.f;

    for (int dg = 0; dg < DP_/4; dg++) {
        float4 p0 = __ldg((const float4*)row0 + dg);
        float4 p1 = __ldg((const float4*)row1 + dg);
        s10 += p0.x + p0.y + p0.z + p0.w;
        s20 += p0.x*p0.x + p0.y*p0.y + p0.z*p0.z + p0.w*p0.w;
        s11 += p1.x + p1.y + p1.z + p1.w;
        s21 += p1.x*p1.x + p1.y*p1.y + p1.z*p1.z + p1.w*p1.w;
#pragma unroll
        for (int h = 0; h < H_; h++) {
            float4 w = *(const float4*)(&Wt[h][dg*4]);
            acc0[h] += p0.x*w.x + p0.y*w.y + p0.z*w.z + p0.w*w.w;
            acc1[h] += p1.x*w.x + p1.y*w.y + p1.z*w.z + p1.w*w.w;
        }
    }

    float mu0 = s10 * (1.f/DP_);
    float mu1 = s11 * (1.f/DP_);
    float r0  = rsqrtf(s20*(1.f/DP_) - mu0*mu0 + 1e-5f);
    float r1  = rsqrtf(s21*(1.f/DP_) - mu1*mu1 + 1e-5f);
    float pb0 = abb[i*MAXS_ + j0];
    float pb1 = abb[i*MAXS_ + j0 + 256];

    int base = ((b*H_)*N_ + i)*N_;
#pragma unroll
    for (int h = 0; h < H_; h++) {
        int o = base + h*(N_*N_);
        g_bias[o + j0]       = r0*(acc0[h] - mu0*c1s[h]) + c2s[h] + pb0;
        g_bias[o + j0 + 256] = r1*(acc1[h] - mu1*c1s[h]) + c2s[h] + pb1;
    }
}

// ---------------------------------------------------------------------------
// K2: QKV+G projections.  C = X[1024x384] @ W[z][384x1024].
// Round-4 proven config: 128x128 tile, BK=8, 8x8 micro, grid (8,8,4).
// ---------------------------------------------------------------------------
__global__ __launch_bounds__(256) void k2_qkvg(
    const float* __restrict__ X,
    const float* __restrict__ wq, const float* __restrict__ wk,
    const float* __restrict__ wv, const float* __restrict__ wg)
{
    __shared__ float As[8][128];
    __shared__ float Bs[8][128];
    int z = blockIdx.z;
    const float* W = (z==0) ? wq : (z==1) ? wk : (z==2) ? wv : wg;
    int m0 = blockIdx.y * 128, n0 = blockIdx.x * 128;
    int tid = threadIdx.x;
    int tx = tid & 15, ty = tid >> 4;

    float acc[8][8];
#pragma unroll
    for (int a = 0; a < 8; a++)
#pragma unroll
        for (int c = 0; c < 8; c++) acc[a][c] = 0.f;

    int ar = tid >> 1, ac = (tid & 1) * 4;
    int bk = tid >> 5, bc = (tid & 31) * 4;

    for (int k0 = 0; k0 < DS_; k0 += 8) {
        float4 av = *(const float4*)(X + (m0+ar)*DS_ + k0 + ac);
        float4 bv = *(const float4*)(W + (k0+bk)*DI_ + n0 + bc);
        __syncthreads();
        As[ac+0][ar] = av.x; As[ac+1][ar] = av.y;
        As[ac+2][ar] = av.z; As[ac+3][ar] = av.w;
        *(float4*)(&Bs[bk][bc]) = bv;
        __syncthreads();
#pragma unroll
        for (int k = 0; k < 8; k++) {
            float a[8], bb[8];
            *(float4*)(&a[0])  = *(const float4*)(&As[k][ty*8]);
            *(float4*)(&a[4])  = *(const float4*)(&As[k][ty*8+4]);
            *(float4*)(&bb[0]) = *(const float4*)(&Bs[k][tx*8]);
            *(float4*)(&bb[4]) = *(const float4*)(&Bs[k][tx*8+4]);
#pragma unroll
            for (int im = 0; im < 8; im++)
#pragma unroll
                for (int in = 0; in < 8; in++)
                    acc[im][in] += a[im]*bb[in];
        }
    }

    if (z == 3) {
#pragma unroll
        for (int im = 0; im < 8; im++) {
            int m = m0 + ty*8 + im;
#pragma unroll
            for (int in = 0; in < 8; in++)
                g_g[m*DI_ + n0 + tx*8 + in] = acc[im][in];
        }
    } else {
        float* dst = (z==0) ? g_q : (z==1) ? g_k : g_v;
#pragma unroll
        for (int im = 0; im < 8; im++) {
            int m = m0 + ty*8 + im;
            int b = m >> 9, n = m & (N_-1);
#pragma unroll
            for (int in = 0; in < 8; in++) {
                int col = n0 + tx*8 + in;
                int h = col >> 6, dh = col & 63;
                dst[((b*H_ + h)*N_ + n)*DH_ + dh] = acc[im][in];
            }
        }
    }
}

// ---------------------------------------------------------------------------
// K35: fused attention per (b,h), VECTORIZED-SMEM version.
// Q and K stored TRANSPOSED in smem so the QK^T loop reads
//   1 LDS.128 (Qs[k][ti*4], broadcast) + 1 LDS.64 (Ks[k][tj*2], conflict-free)
// per 8 FMA (ratio 4; was 6 scalar LDS per 8 FMA = 1.33).
// Ps pitch 68 -> PV loop reads 2 LDS.128 per 16 FMA (ratio 8; was 3.2).
// smem = 42.5 KB. grid (8, 32), 256 threads.
// ---------------------------------------------------------------------------
__global__ __launch_bounds__(256) void k35_attn()
{
    __shared__ float Qs[64][68];   // [k][i], pitch 68 -> aligned float4 reads
    __shared__ float Ks[64][36];   // [k][j], pitch 36 -> aligned float2 reads
    __shared__ float Vs[32][64];   // [j][d]
    __shared__ float Ps[32][68];   // [j][i], pitch 68 -> aligned float4 reads

    int z  = blockIdx.y;                    // b*16 + h
    int i0 = blockIdx.x * 64;
    const float* Q  = g_q + (long)z * (N_*DH_);
    const float* K  = g_k + (long)z * (N_*DH_);
    const float* V  = g_v + (long)z * (N_*DH_);
    const float* Bb = g_bias + (long)z * N_ * N_;

    int tid = threadIdx.x;
    int ti = tid >> 4;      // 0..15 -> i rows ti*4..ti*4+3
    int tj = tid & 15;      // 0..15 -> j cols tj*2..+1 / d cols tj*4..+3

    // Load Q tile transposed: Qs[k][i]. lane = i (conflict-free STS).
    {
        int r  = tid & 63;           // i row
        int c0 = (tid >> 6) * 16;    // k group (16 cols = 4 float4)
#pragma unroll
        for (int q = 0; q < 4; q++) {
            float4 v = *(const float4*)(Q + (i0 + r)*DH_ + c0 + q*4);
            Qs[c0+q*4+0][r] = v.x;
            Qs[c0+q*4+1][r] = v.y;
            Qs[c0+q*4+2][r] = v.z;
            Qs[c0+q*4+3][r] = v.w;
        }
    }

    float m_run[4], l_run[4], o[4][4];
#pragma unroll
    for (int a = 0; a < 4; a++) {
        m_run[a] = -1e30f; l_run[a] = 0.f;
#pragma unroll
        for (int c = 0; c < 4; c++) o[a][c] = 0.f;
    }
    __syncthreads();

    for (int j0 = 0; j0 < N_; j0 += 32) {
        // K transposed store: lane = j (conflict-free STS into Ks[k][j]).
        {
            int r = tid & 31;            // j
            int c = (tid >> 5) * 8;      // k group
            float4 ka = *(const float4*)(K + (j0 + r)*DH_ + c);
            float4 kb = *(const float4*)(K + (j0 + r)*DH_ + c + 4);
            Ks[c+0][r] = ka.x; Ks[c+1][r] = ka.y; Ks[c+2][r] = ka.z; Ks[c+3][r] = ka.w;
            Ks[c+4][r] = kb.x; Ks[c+5][r] = kb.y; Ks[c+6][r] = kb.z; Ks[c+7][r] = kb.w;
        }
        // V row-major float4 store (original mapping).
        {
            int r = tid >> 3;            // 0..31
            int c = (tid & 7) * 8;
            float4 va = *(const float4*)(V + (j0 + r)*DH_ + c);
            float4 vb = *(const float4*)(V + (j0 + r)*DH_ + c + 4);
            *(float4*)(&Vs[r][c])   = va;
            *(float4*)(&Vs[r][c+4]) = vb;
        }
        __syncthreads();

        // S = Q K^T: per k, 1 LDS.128 + 1 LDS.64 + 8 FMA.
        float s[4][2];
#pragma unroll
        for (int a = 0; a < 4; a++) { s[a][0] = 0.f; s[a][1] = 0.f; }
#pragma unroll 8
        for (int k = 0; k < 64; k++) {
            float4 qv = *(const float4*)(&Qs[k][ti*4]);
            float2 kv = *(const float2*)(&Ks[k][tj*2]);
            s[0][0] += qv.x*kv.x; s[0][1] += qv.x*kv.y;
            s[1][0] += qv.y*kv.x; s[1][1] += qv.y*kv.y;
            s[2][0] += qv.z*kv.x; s[2][1] += qv.z*kv.y;
            s[3][0] += qv.w*kv.x; s[3][1] += qv.w*kv.y;
        }

        // scale + bias, online softmax update (rows split across 16 tj lanes)
#pragma unroll
        for (int a = 0; a < 4; a++) {
            const float* br = Bb + (long)(i0 + ti*4 + a)*N_ + j0 + tj*2;
            s[a][0] = s[a][0]*0.125f + br[0];
            s[a][1] = s[a][1]*0.125f + br[1];

            float cm = fmaxf(s[a][0], s[a][1]);
#pragma unroll
            for (int sft = 8; sft > 0; sft >>= 1)
                cm = fmaxf(cm, __shfl_xor_sync(0xffffffffu, cm, sft, 16));
            float mn = fmaxf(m_run[a], cm);
            float sc = __expf(m_run[a] - mn);
            float e0 = __expf(s[a][0] - mn);
            float e1 = __expf(s[a][1] - mn);
            float cs = e0 + e1;
#pragma unroll
            for (int sft = 8; sft > 0; sft >>= 1)
                cs += __shfl_xor_sync(0xffffffffu, cs, sft, 16);
            l_run[a] = l_run[a]*sc + cs;
            m_run[a] = mn;
#pragma unroll
            for (int c = 0; c < 4; c++) o[a][c] *= sc;
            s[a][0] = e0; s[a][1] = e1;
        }

        // store P transposed: Ps[j][i] (scalar stores, pitch 68)
#pragma unroll
        for (int a = 0; a < 4; a++) {
            Ps[tj*2+0][ti*4+a] = s[a][0];
            Ps[tj*2+1][ti*4+a] = s[a][1];
        }
        __syncthreads();

        // O += P @ V: per j, 2 LDS.128 + 16 FMA.
#pragma unroll 8
        for (int j = 0; j < 32; j++) {
            float4 pv = *(const float4*)(&Ps[j][ti*4]);
            float4 vv = *(const float4*)(&Vs[j][tj*4]);
            o[0][0] += pv.x*vv.x; o[0][1] += pv.x*vv.y; o[0][2] += pv.x*vv.z; o[0][3] += pv.x*vv.w;
            o[1][0] += pv.y*vv.x; o[1][1] += pv.y*vv.y; o[1][2] += pv.y*vv.z; o[1][3] += pv.y*vv.w;
            o[2][0] += pv.z*vv.x; o[2][1] += pv.z*vv.y; o[2][2] += pv.z*vv.z; o[2][3] += pv.z*vv.w;
            o[3][0] += pv.w*vv.x; o[3][1] += pv.w*vv.y; o[3][2] += pv.w*vv.z; o[3][3] += pv.w*vv.w;
        }
        __syncthreads();
    }

    // epilogue: normalize, write [b][n][h*64+d]
    int b = z >> 4, h = z & 15;
#pragma unroll
    for (int a = 0; a < 4; a++) {
        float inv = 1.f / l_run[a];
        int i = i0 + ti*4 + a;
#pragma unroll
        for (int c = 0; c < 4; c++)
            g_o[(long)(b*N_ + i)*DI_ + h*DH_ + tj*4 + c] = o[a][c] * inv;
    }
}

// ---------------------------------------------------------------------------
// K6: out_part = (o * sigmoid(g)) @ w_o, SPLIT-K=4 with 4x4 microtile.
// BM=64, BN=64, BK=16. grid (6,16,4)=384 blocks (ratio 8 AND 2.6 blocks/SM:
// round-12 showed ratio fix alone left occ at 16.5% / 52us; need both).
// ---------------------------------------------------------------------------
__global__ __launch_bounds__(256) void k6_out(const float* __restrict__ wo)
{
    __shared__ float As[16][68];   // transposed [k][m]; pitch 68 -> float4-aligned reads
    __shared__ float Bs[16][64];
    int m0 = blockIdx.y * 64, n0 = blockIdx.x * 64;
    int kh = blockIdx.z;
    int kbase = kh * (DI_/4);
    int tid = threadIdx.x;
    int tx = tid & 15, ty = tid >> 4;
    int ar = tid >> 2, ac = (tid & 3) * 4;    // A: 64 rows x 16 k
    int bk = tid >> 4, bc = (tid & 15) * 4;   // B: 16 k x 64 n

    float acc[4][4];
#pragma unroll
    for (int a = 0; a < 4; a++)
#pragma unroll
        for (int c = 0; c < 4; c++) acc[a][c] = 0.f;

    for (int kk = 0; kk < DI_/4; kk += 16) {
        int k0 = kbase + kk;
        float4 ov = *(const float4*)(g_o + (m0+ar)*DI_ + k0 + ac);
        float4 gv = *(const float4*)(g_g + (m0+ar)*DI_ + k0 + ac);
        float4 bv = *(const float4*)(wo + (k0+bk)*DS_ + n0 + bc);
        float4 a;
        a.x = ov.x / (1.f + __expf(-gv.x));
        a.y = ov.y / (1.f + __expf(-gv.y));
        a.z = ov.z / (1.f + __expf(-gv.z));
        a.w = ov.w / (1.f + __expf(-gv.w));
        __syncthreads();
        As[ac+0][ar] = a.x; As[ac+1][ar] = a.y;
        As[ac+2][ar] = a.z; As[ac+3][ar] = a.w;
        *(float4*)(&Bs[bk][bc]) = bv;
        __syncthreads();
#pragma unroll
        for (int k = 0; k < 16; k++) {
            float4 av = *(const float4*)(&As[k][ty*4]);
            float4 b  = *(const float4*)(&Bs[k][tx*4]);
            acc[0][0] += av.x*b.x; acc[0][1] += av.x*b.y; acc[0][2] += av.x*b.z; acc[0][3] += av.x*b.w;
            acc[1][0] += av.y*b.x; acc[1][1] += av.y*b.y; acc[1][2] += av.y*b.z; acc[1][3] += av.y*b.w;
            acc[2][0] += av.z*b.x; acc[2][1] += av.z*b.y; acc[2][2] += av.z*b.z; acc[2][3] += av.z*b.w;
            acc[3][0] += av.w*b.x; acc[3][1] += av.w*b.y; acc[3][2] += av.w*b.z; acc[3][3] += av.w*b.w;
        }
    }

#pragma unroll
    for (int ii = 0; ii < 4; ii++) {
        float4 v = make_float4(acc[ii][0], acc[ii][1], acc[ii][2], acc[ii][3]);
        *(float4*)(&g_part[kh][m0 + ty*4 + ii][n0 + tx*4]) = v;
    }
}

// ---------------------------------------------------------------------------
// K6R: out = sum of 4 partials. 1024*384 floats = 98304 float4.
// ---------------------------------------------------------------------------
__global__ __launch_bounds__(256) void k6_reduce(float* __restrict__ out)
{
    int idx = blockIdx.x * 256 + threadIdx.x;   // float4 index
    const float4* p0 = (const float4*)&g_part[0][0][0];
    const float4* p1 = (const float4*)&g_part[1][0][0];
    const float4* p2 = (const float4*)&g_part[2][0][0];
    const float4* p3 = (const float4*)&g_part[3][0][0];
    float4 a = p0[idx], b = p1[idx], c = p2[idx], d = p3[idx];
    float4 r = make_float4(a.x+b.x+c.x+d.x, a.y+b.y+c.y+d.y,
                           a.z+b.z+c.z+d.z, a.w+b.w+c.w+d.w);
    ((float4*)out)[idx] = r;
}

// ---------------------------------------------------------------------------
extern "C" void kernel_launch(void* const* d_in, const int* in_sizes, int n_in,
                              void* d_out, int out_size) {
    const float* single = (const float*)d_in[0];
    const float* pw     = (const float*)d_in[1];
    const float* gamma  = (const float*)d_in[2];
    const float* beta   = (const float*)d_in[3];
    const float* wb     = (const float*)d_in[4];
    const float* abb    = (const float*)d_in[5];
    const float* wq     = (const float*)d_in[6];
    const float* wk     = (const float*)d_in[7];
    const float* wv     = (const float*)d_in[8];
    const float* wg     = (const float*)d_in[9];
    const float* wo     = (const float*)d_in[10];
    float* out = (float*)d_out;

    k1_ln_bias<<<B_*N_, 256>>>(pw, gamma, beta, wb, abb);
    k2_qkvg<<<dim3(8, 8, 4), 256>>>(single, wq, wk, wv, wg);
    k35_attn<<<dim3(8, 32), 256>>>();
    k6_out<<<dim3(6, 16, 4), 256>>>(wo);
    k6_reduce<<<(B_*N_*DS_)/(4*256), 256>>>(out);
}

// round 15
// speedup vs baseline: 1.1441x; 1.0047x over previous
#include <cuda_runtime.h>

#define B_    2
#define N_    512
#define DS_   384
#define DP_   128
#define H_    16
#define DH_   64
#define DI_   1024
#define MAXS_ 2048

typedef unsigned long long u64;

// ---- packed f32x2 helpers (Blackwell: fma.rn.f32x2, PTX-only) --------------
__device__ __forceinline__ u64 pk2(float lo, float hi) {
    u64 r; asm("mov.b64 %0, {%1,%2};" : "=l"(r) : "f"(lo), "f"(hi)); return r;
}
__device__ __forceinline__ void upk2(u64 v, float &lo, float &hi) {
    asm("mov.b64 {%0,%1}, %2;" : "=f"(lo), "=f"(hi) : "l"(v));
}
__device__ __forceinline__ void fma2(u64 &d, u64 a, u64 b) {
    asm("fma.rn.f32x2 %0, %1, %2, %0;" : "+l"(d) : "l"(a), "l"(b));
}
__device__ __forceinline__ void mul2(u64 &d, u64 a) {
    asm("mul.rn.f32x2 %0, %0, %1;" : "+l"(d) : "l"(a));
}

// ---------------- scratch (static device globals; no allocs) ----------------
__device__ float g_bias[B_*H_*N_*N_];   // attn bias  [b][h][i][j]
__device__ float g_q[B_*H_*N_*DH_];     // [b][h][n][d]
__device__ float g_k[B_*H_*N_*DH_];
__device__ float g_v[B_*H_*N_*DH_];
__device__ float g_g[B_*N_*DI_];        // gate logits [b][n][di]
__device__ float g_o[B_*N_*DI_];        // attention out [b][n][di]
__device__ float g_part[4][B_*N_][DS_]; // split-K partials for output proj

// ---------------------------------------------------------------------------
// K1: fused LayerNorm + per-head bias projection + positional bias (scalar)
// ---------------------------------------------------------------------------
__global__ __launch_bounds__(256) void k1_ln_bias(
    const float* __restrict__ pw, const float* __restrict__ gamma,
    const float* __restrict__ beta, const float* __restrict__ wb,
    const float* __restrict__ abb)
{
    __shared__ float Wt[H_][DP_];
    __shared__ float c1s[H_], c2s[H_];
    int tid = threadIdx.x;

    for (int idx = tid; idx < DP_*H_; idx += 256) {
        int d = idx >> 4, h = idx & 15;
        Wt[h][d] = gamma[d] * wb[d*H_ + h];
    }
    __syncthreads();
    if (tid < H_) {
        float a = 0.f, c = 0.f;
        for (int d = 0; d < DP_; d++) {
            a += Wt[tid][d];
            c += beta[d] * wb[d*H_ + tid];
        }
        c1s[tid] = a; c2s[tid] = c;
    }
    __syncthreads();

    int bi = blockIdx.x;            // b*N + i
    int i  = bi & (N_-1);
    int b  = bi >> 9;
    int j0 = tid;

    const float* row0 = pw + ((long)bi * N_ + j0) * DP_;
    const float* row1 = row0 + 256 * DP_;

    float acc0[H_], acc1[H_];
#pragma unroll
    for (int h = 0; h < H_; h++) { acc0[h] = 0.f; acc1[h] = 0.f; }
    float s10 = 0.f, s20 = 0.f, s11 = 0.f, s21 = 0.f;

    for (int dg = 0; dg < DP_/4; dg++) {
        float4 p0 = __ldg((const float4*)row0 + dg);
        float4 p1 = __ldg((const float4*)row1 + dg);
        s10 += p0.x + p0.y + p0.z + p0.w;
        s20 += p0.x*p0.x + p0.y*p0.y + p0.z*p0.z + p0.w*p0.w;
        s11 += p1.x + p1.y + p1.z + p1.w;
        s21 += p1.x*p1.x + p1.y*p1.y + p1.z*p1.z + p1.w*p1.w;
#pragma unroll
        for (int h = 0; h < H_; h++) {
            float4 w = *(const float4*)(&Wt[h][dg*4]);
            acc0[h] += p0.x*w.x + p0.y*w.y + p0.z*w.z + p0.w*w.w;
            acc1[h] += p1.x*w.x + p1.y*w.y + p1.z*w.z + p1.w*w.w;
        }
    }

    float mu0 = s10 * (1.f/DP_);
    float mu1 = s11 * (1.f/DP_);
    float r0  = rsqrtf(s20*(1.f/DP_) - mu0*mu0 + 1e-5f);
    float r1  = rsqrtf(s21*(1.f/DP_) - mu1*mu1 + 1e-5f);
    float pb0 = abb[i*MAXS_ + j0];
    float pb1 = abb[i*MAXS_ + j0 + 256];

    int base = ((b*H_)*N_ + i)*N_;
#pragma unroll
    for (int h = 0; h < H_; h++) {
        int o = base + h*(N_*N_);
        g_bias[o + j0]       = r0*(acc0[h] - mu0*c1s[h]) + c2s[h] + pb0;
        g_bias[o + j0 + 256] = r1*(acc1[h] - mu1*c1s[h]) + c2s[h] + pb1;
    }
}

// ---------------------------------------------------------------------------
// K2: QKV+G projections, PACKED-FMA version.
// 128x128 tile, BK=8, 8x8 micro, grid (8,8,4).
// Per k: 4 LDS.128 + 12 mov.b64 (ALU) + 32 fma.rn.f32x2 (was 64 FFMA).
// ---------------------------------------------------------------------------
__global__ __launch_bounds__(256) void k2_qkvg(
    const float* __restrict__ X,
    const float* __restrict__ wq, const float* __restrict__ wk,
    const float* __restrict__ wv, const float* __restrict__ wg)
{
    __shared__ float As[8][128];
    __shared__ float Bs[8][128];
    int z = blockIdx.z;
    const float* W = (z==0) ? wq : (z==1) ? wk : (z==2) ? wv : wg;
    int m0 = blockIdx.y * 128, n0 = blockIdx.x * 128;
    int tid = threadIdx.x;
    int tx = tid & 15, ty = tid >> 4;

    u64 acc2[8][4];
#pragma unroll
    for (int a = 0; a < 8; a++)
#pragma unroll
        for (int c = 0; c < 4; c++) acc2[a][c] = 0ull;

    int ar = tid >> 1, ac = (tid & 1) * 4;
    int bk = tid >> 5, bc = (tid & 31) * 4;

    for (int k0 = 0; k0 < DS_; k0 += 8) {
        float4 av = *(const float4*)(X + (m0+ar)*DS_ + k0 + ac);
        float4 bv = *(const float4*)(W + (k0+bk)*DI_ + n0 + bc);
        __syncthreads();
        As[ac+0][ar] = av.x; As[ac+1][ar] = av.y;
        As[ac+2][ar] = av.z; As[ac+3][ar] = av.w;
        *(float4*)(&Bs[bk][bc]) = bv;
        __syncthreads();
#pragma unroll
        for (int k = 0; k < 8; k++) {
            float a[8];
            *(float4*)(&a[0]) = *(const float4*)(&As[k][ty*8]);
            *(float4*)(&a[4]) = *(const float4*)(&As[k][ty*8+4]);
            // B pairs come free: aligned 16B reads reinterpreted as 2x u64
            ulonglong2 b01 = *(const ulonglong2*)(&Bs[k][tx*8]);
            ulonglong2 b23 = *(const ulonglong2*)(&Bs[k][tx*8+4]);
            u64 bb2[4] = { b01.x, b01.y, b23.x, b23.y };
#pragma unroll
            for (int im = 0; im < 8; im++) {
                u64 a2 = pk2(a[im], a[im]);
#pragma unroll
                for (int p = 0; p < 4; p++)
                    fma2(acc2[im][p], a2, bb2[p]);
            }
        }
    }

    if (z == 3) {
#pragma unroll
        for (int im = 0; im < 8; im++) {
            int m = m0 + ty*8 + im;
#pragma unroll
            for (int p = 0; p < 4; p++) {
                float c0, c1; upk2(acc2[im][p], c0, c1);
                g_g[m*DI_ + n0 + tx*8 + 2*p]     = c0;
                g_g[m*DI_ + n0 + tx*8 + 2*p + 1] = c1;
            }
        }
    } else {
        float* dst = (z==0) ? g_q : (z==1) ? g_k : g_v;
#pragma unroll
        for (int im = 0; im < 8; im++) {
            int m = m0 + ty*8 + im;
            int b = m >> 9, n = m & (N_-1);
#pragma unroll
            for (int p = 0; p < 4; p++) {
                float c0, c1; upk2(acc2[im][p], c0, c1);
                int col0 = n0 + tx*8 + 2*p;
                int h0 = col0 >> 6, dh0 = col0 & 63;
                dst[((b*H_ + h0)*N_ + n)*DH_ + dh0] = c0;
                int col1 = col0 + 1;
                int h1 = col1 >> 6, dh1 = col1 & 63;
                dst[((b*H_ + h1)*N_ + n)*DH_ + dh1] = c1;
            }
        }
    }
}

// ---------------------------------------------------------------------------
// K35: fused attention per (b,h), PACKED-FMA version.
// QK loop: 2 LDS + 2 mov + 4 fma2 per k (was 8 FFMA on FMA pipe).
// PV loop: 2 LDS + 4 mov + 8 fma2 per j (was 16 FFMA).
// smem layouts as round-13 (Qs/Ks transposed, all 16B-aligned vec reads).
// ---------------------------------------------------------------------------
__global__ __launch_bounds__(256) void k35_attn()
{
    __shared__ float Qs[64][68];   // [k][i]
    __shared__ float Ks[64][36];   // [k][j]
    __shared__ float Vs[32][64];   // [j][d]
    __shared__ float Ps[32][68];   // [j][i]

    int z  = blockIdx.y;                    // b*16 + h
    int i0 = blockIdx.x * 64;
    const float* Q  = g_q + (long)z * (N_*DH_);
    const float* K  = g_k + (long)z * (N_*DH_);
    const float* V  = g_v + (long)z * (N_*DH_);
    const float* Bb = g_bias + (long)z * N_ * N_;

    int tid = threadIdx.x;
    int ti = tid >> 4;      // i rows ti*4..+3
    int tj = tid & 15;      // j cols tj*2..+1 / d cols tj*4..+3

    // Load Q tile transposed: Qs[k][i]. lane = i (conflict-free STS).
    {
        int r  = tid & 63;
        int c0 = (tid >> 6) * 16;
#pragma unroll
        for (int q = 0; q < 4; q++) {
            float4 v = *(const float4*)(Q + (i0 + r)*DH_ + c0 + q*4);
            Qs[c0+q*4+0][r] = v.x;
            Qs[c0+q*4+1][r] = v.y;
            Qs[c0+q*4+2][r] = v.z;
            Qs[c0+q*4+3][r] = v.w;
        }
    }

    float m_run[4], l_run[4];
    u64 o2[4][2];                 // [i-row a][d-pair]
#pragma unroll
    for (int a = 0; a < 4; a++) {
        m_run[a] = -1e30f; l_run[a] = 0.f;
        o2[a][0] = 0ull; o2[a][1] = 0ull;
    }
    __syncthreads();

    for (int j0 = 0; j0 < N_; j0 += 32) {
        // K transposed store: lane = j.
        {
            int r = tid & 31;
            int c = (tid >> 5) * 8;
            float4 ka = *(const float4*)(K + (j0 + r)*DH_ + c);
            float4 kb = *(const float4*)(K + (j0 + r)*DH_ + c + 4);
            Ks[c+0][r] = ka.x; Ks[c+1][r] = ka.y; Ks[c+2][r] = ka.z; Ks[c+3][r] = ka.w;
            Ks[c+4][r] = kb.x; Ks[c+5][r] = kb.y; Ks[c+6][r] = kb.z; Ks[c+7][r] = kb.w;
        }
        // V row-major float4 store.
        {
            int r = tid >> 3;
            int c = (tid & 7) * 8;
            float4 va = *(const float4*)(V + (j0 + r)*DH_ + c);
            float4 vb = *(const float4*)(V + (j0 + r)*DH_ + c + 4);
            *(float4*)(&Vs[r][c])   = va;
            *(float4*)(&Vs[r][c+4]) = vb;
        }
        __syncthreads();

        // S = Q K^T, packed over i-pairs: s2[jj][p] = (i=2p, i=2p+1).
        u64 s2[2][2] = {{0ull,0ull},{0ull,0ull}};
#pragma unroll 8
        for (int k = 0; k < 64; k++) {
            ulonglong2 qp = *(const ulonglong2*)(&Qs[k][ti*4]);  // (q0,q1),(q2,q3)
            float2 kv = *(const float2*)(&Ks[k][tj*2]);
            u64 kx2 = pk2(kv.x, kv.x);
            u64 ky2 = pk2(kv.y, kv.y);
            fma2(s2[0][0], qp.x, kx2); fma2(s2[0][1], qp.y, kx2);
            fma2(s2[1][0], qp.x, ky2); fma2(s2[1][1], qp.y, ky2);
        }
        float s[4][2];
        upk2(s2[0][0], s[0][0], s[1][0]); upk2(s2[0][1], s[2][0], s[3][0]);
        upk2(s2[1][0], s[0][1], s[1][1]); upk2(s2[1][1], s[2][1], s[3][1]);

        // scale + bias, online softmax update
#pragma unroll
        for (int a = 0; a < 4; a++) {
            const float* br = Bb + (long)(i0 + ti*4 + a)*N_ + j0 + tj*2;
            s[a][0] = s[a][0]*0.125f + br[0];
            s[a][1] = s[a][1]*0.125f + br[1];

            float cm = fmaxf(s[a][0], s[a][1]);
#pragma unroll
            for (int sft = 8; sft > 0; sft >>= 1)
                cm = fmaxf(cm, __shfl_xor_sync(0xffffffffu, cm, sft, 16));
            float mn = fmaxf(m_run[a], cm);
            float sc = __expf(m_run[a] - mn);
            float e0 = __expf(s[a][0] - mn);
            float e1 = __expf(s[a][1] - mn);
            float cs = e0 + e1;
#pragma unroll
            for (int sft = 8; sft > 0; sft >>= 1)
                cs += __shfl_xor_sync(0xffffffffu, cs, sft, 16);
            l_run[a] = l_run[a]*sc + cs;
            m_run[a] = mn;
            u64 sc2 = pk2(sc, sc);
            mul2(o2[a][0], sc2);
            mul2(o2[a][1], sc2);
            s[a][0] = e0; s[a][1] = e1;
        }

        // store P transposed: Ps[j][i]
#pragma unroll
        for (int a = 0; a < 4; a++) {
            Ps[tj*2+0][ti*4+a] = s[a][0];
            Ps[tj*2+1][ti*4+a] = s[a][1];
        }
        __syncthreads();

        // O += P @ V, packed over d-pairs.
#pragma unroll 8
        for (int j = 0; j < 32; j++) {
            float4 pv = *(const float4*)(&Ps[j][ti*4]);
            ulonglong2 vv = *(const ulonglong2*)(&Vs[j][tj*4]);   // (v0,v1),(v2,v3)
            u64 p0b = pk2(pv.x, pv.x), p1b = pk2(pv.y, pv.y);
            u64 p2b = pk2(pv.z, pv.z), p3b = pk2(pv.w, pv.w);
            fma2(o2[0][0], p0b, vv.x); fma2(o2[0][1], p0b, vv.y);
            fma2(o2[1][0], p1b, vv.x); fma2(o2[1][1], p1b, vv.y);
            fma2(o2[2][0], p2b, vv.x); fma2(o2[2][1], p2b, vv.y);
            fma2(o2[3][0], p3b, vv.x); fma2(o2[3][1], p3b, vv.y);
        }
        __syncthreads();
    }

    // epilogue: normalize, write [b][n][h*64+d]
    int b = z >> 4, h = z & 15;
#pragma unroll
    for (int a = 0; a < 4; a++) {
        float inv = 1.f / l_run[a];
        int i = i0 + ti*4 + a;
        float o0, o1, o2f, o3;
        upk2(o2[a][0], o0, o1);
        upk2(o2[a][1], o2f, o3);
        float* dst = g_o + (long)(b*N_ + i)*DI_ + h*DH_ + tj*4;
        dst[0] = o0 * inv; dst[1] = o1 * inv;
        dst[2] = o2f * inv; dst[3] = o3 * inv;
    }
}

// ---------------------------------------------------------------------------
// K6: out_part = (o * sigmoid(g)) @ w_o, SPLIT-K=4, PACKED-FMA 4x4 micro.
// grid (6,16,4)=384 blocks. Per k: 2 LDS + 6 mov + 8 fma2 (was 16 FFMA).
// ---------------------------------------------------------------------------
__global__ __launch_bounds__(256) void k6_out(const float* __restrict__ wo)
{
    __shared__ float As[16][68];
    __shared__ float Bs[16][64];
    int m0 = blockIdx.y * 64, n0 = blockIdx.x * 64;
    int kh = blockIdx.z;
    int kbase = kh * (DI_/4);
    int tid = threadIdx.x;
    int tx = tid & 15, ty = tid >> 4;
    int ar = tid >> 2, ac = (tid & 3) * 4;
    int bk = tid >> 4, bc = (tid & 15) * 4;

    u64 acc2[4][2];
#pragma unroll
    for (int a = 0; a < 4; a++) { acc2[a][0] = 0ull; acc2[a][1] = 0ull; }

    for (int kk = 0; kk < DI_/4; kk += 16) {
        int k0 = kbase + kk;
        float4 ov = *(const float4*)(g_o + (m0+ar)*DI_ + k0 + ac);
        float4 gv = *(const float4*)(g_g + (m0+ar)*DI_ + k0 + ac);
        float4 bv = *(const float4*)(wo + (k0+bk)*DS_ + n0 + bc);
        float4 a;
        a.x = ov.x / (1.f + __expf(-gv.x));
        a.y = ov.y / (1.f + __expf(-gv.y));
        a.z = ov.z / (1.f + __expf(-gv.z));
        a.w = ov.w / (1.f + __expf(-gv.w));
        __syncthreads();
        As[ac+0][ar] = a.x; As[ac+1][ar] = a.y;
        As[ac+2][ar] = a.z; As[ac+3][ar] = a.w;
        *(float4*)(&Bs[bk][bc]) = bv;
        __syncthreads();
#pragma unroll
        for (int k = 0; k < 16; k++) {
            float4 av = *(const float4*)(&As[k][ty*4]);
            ulonglong2 b2 = *(const ulonglong2*)(&Bs[k][tx*4]);   // (b0,b1),(b2,b3)
            u64 a0 = pk2(av.x, av.x), a1 = pk2(av.y, av.y);
            u64 a2 = pk2(av.z, av.z), a3 = pk2(av.w, av.w);
            fma2(acc2[0][0], a0, b2.x); fma2(acc2[0][1], a0, b2.y);
            fma2(acc2[1][0], a1, b2.x); fma2(acc2[1][1], a1, b2.y);
            fma2(acc2[2][0], a2, b2.x); fma2(acc2[2][1], a2, b2.y);
            fma2(acc2[3][0], a3, b2.x); fma2(acc2[3][1], a3, b2.y);
        }
    }

#pragma unroll
    for (int ii = 0; ii < 4; ii++) {
        float c0, c1, c2, c3;
        upk2(acc2[ii][0], c0, c1);
        upk2(acc2[ii][1], c2, c3);
        float4 v = make_float4(c0, c1, c2, c3);
        *(float4*)(&g_part[kh][m0 + ty*4 + ii][n0 + tx*4]) = v;
    }
}

// ---------------------------------------------------------------------------
// K6R: out = sum of 4 partials.
// ---------------------------------------------------------------------------
__global__ __launch_bounds__(256) void k6_reduce(float* __restrict__ out)
{
    int idx = blockIdx.x * 256 + threadIdx.x;   // float4 index
    const float4* p0 = (const float4*)&g_part[0][0][0];
    const float4* p1 = (const float4*)&g_part[1][0][0];
    const float4* p2 = (const float4*)&g_part[2][0][0];
    const float4* p3 = (const float4*)&g_part[3][0][0];
    float4 a = p0[idx], b = p1[idx], c = p2[idx], d = p3[idx];
    float4 r = make_float4(a.x+b.x+c.x+d.x, a.y+b.y+c.y+d.y,
                           a.z+b.z+c.z+d.z, a.w+b.w+c.w+d.w);
    ((float4*)out)[idx] = r;
}

// ---------------------------------------------------------------------------
extern "C" void kernel_launch(void* const* d_in, const int* in_sizes, int n_in,
                              void* d_out, int out_size) {
    const float* single = (const float*)d_in[0];
    const float* pw     = (const float*)d_in[1];
    const float* gamma  = (const float*)d_in[2];
    const float* beta   = (const float*)d_in[3];
    const float* wb     = (const float*)d_in[4];
    const float* abb    = (const float*)d_in[5];
    const float* wq     = (const float*)d_in[6];
    const float* wk     = (const float*)d_in[7];
    const float* wv     = (const float*)d_in[8];
    const float* wg     = (const float*)d_in[9];
    const float* wo     = (const float*)d_in[10];
    float* out = (float*)d_out;

    k1_ln_bias<<<B_*N_, 256>>>(pw, gamma, beta, wb, abb);
    k2_qkvg<<<dim3(8, 8, 4), 256>>>(single, wq, wk, wv, wg);
    k35_attn<<<dim3(8, 32), 256>>>();
    k6_out<<<dim3(6, 16, 4), 256>>>(wo);
    k6_reduce<<<(B_*N_*DS_)/(4*256), 256>>>(out);
}